// round 17
// baseline (speedup 1.0000x reference)
#include <cuda_runtime.h>
#include <cuda_fp16.h>

// Problem constants
#define T_    256
#define B_    256
#define H_    1024
#define E_    300
#define FEAT  319
#define FEATP 320
#define C_    13
#define G4H   4096
#define M_    (T_ * B_)

#define SCAN_NCTA 128
// scan smem (halves): Ws [64][1032] + Wx [64][328] + Hs [3][128][72] + Bs(64 f32)
#define SCAN_WS_HALF (64 * 1032)
#define SCAN_WX_HALF (64 * 328)
#define SCAN_HS_HALF (3 * 128 * 72)
#define SCAN_SMEM ((SCAN_WS_HALF + SCAN_WX_HALF + SCAN_HS_HALF) * 2 + 64 * 4)
// lstm1: 3 stages x (A[256][40] + B[128][40]) halves = 92160 B, 2 CTAs/SM
#define L1_STAGE_HALF (256 * 40 + 128 * 40)
#define L1_SMEM (3 * L1_STAGE_HALF * 2)
// decode: 3 stages x (A[256][40] + B[16][40]) halves
#define DC_STAGE_HALF (256 * 40 + 16 * 40)
#define DC_SMEM (3 * DC_STAGE_HALF * 2)

// -------- scratch (static device globals; no allocation anywhere) --------
__device__ __half g_Xh[(size_t)M_ * FEATP];
__device__ __half g_wi0ph[(size_t)G4H * FEATP];
__device__ __half g_h0h[(size_t)M_ * H_];
__device__ __half g_h1h[(size_t)M_ * H_];
__device__ __half g_c0h[(size_t)M_ * H_];
__device__ __half g_w1h[2][(size_t)G4H * H_];   // wi1, wh1 as fp16
__device__ __half g_hinith[(size_t)B_ * H_];
__device__ __half g_dwh[16 * 2 * H_];           // dec_w fp16, rows 13..15 zero
__device__ unsigned g_cnt[2];                   // per row-group step counters

__device__ __forceinline__ float sigmoidf_(float x) {
    return 1.0f / (1.0f + __expf(-x));
}
// fp16 m16n8k16, fp32 accumulate
__device__ __forceinline__ void mma16(float* d, const unsigned* a, const unsigned* b) {
    asm volatile(
        "mma.sync.aligned.m16n8k16.row.col.f32.f16.f16.f32 "
        "{%0,%1,%2,%3}, {%4,%5,%6,%7}, {%8,%9}, {%0,%1,%2,%3};\n"
        : "+f"(d[0]), "+f"(d[1]), "+f"(d[2]), "+f"(d[3])
        : "r"(a[0]), "r"(a[1]), "r"(a[2]), "r"(a[3]), "r"(b[0]), "r"(b[1]));
}
__device__ __forceinline__ void ldsm4(unsigned* d, unsigned a) {
    asm volatile("ldmatrix.sync.aligned.m8n8.x4.shared.b16 {%0,%1,%2,%3}, [%4];"
                 : "=r"(d[0]), "=r"(d[1]), "=r"(d[2]), "=r"(d[3]) : "r"(a));
}
__device__ __forceinline__ void cpa16(void* sdst, const void* gsrc) {
    unsigned s = (unsigned)__cvta_generic_to_shared(sdst);
    asm volatile("cp.async.cg.shared.global [%0], [%1], 16;\n" :: "r"(s), "l"(gsrc));
}
#define CP_COMMIT() asm volatile("cp.async.commit_group;\n" ::: "memory")
template <int N> __device__ __forceinline__ void cp_wait() {
    asm volatile("cp.async.wait_group %0;\n" :: "n"(N) : "memory");
}
__device__ __forceinline__ unsigned ldv(const unsigned* p) {
    unsigned v;
    asm volatile("ld.volatile.global.u32 %0, [%1];" : "=r"(v) : "l"(p));
    return v;
}
__device__ __forceinline__ unsigned smem_u32(const void* p) {
    return (unsigned)__cvta_generic_to_shared(p);
}

__global__ void k_reset() { g_cnt[threadIdx.x] = 0u; }

// ===========================================================================
// Kernel 1 (fused prep): X fp16, wi0 pad fp16, h_init fp16, wi1/wh1 fp16,
// dec_w fp16 (rows 13..15 zero).
// ===========================================================================
__global__ void k_build(const int* __restrict__ tokens,
                        const float* __restrict__ casing,
                        const float* __restrict__ pos,
                        const float* __restrict__ emb,
                        const float* __restrict__ wi0,
                        const float* __restrict__ wi1,
                        const float* __restrict__ wh1,
                        const float* __restrict__ h_init0,
                        const float* __restrict__ dec_w) {
    int b = blockIdx.x;
    if (b < M_) {
        int tok = tokens[b];
        const float* erow = emb + (size_t)tok * E_;
        __half* xrow = g_Xh + (size_t)b * FEATP;
        for (int k = threadIdx.x; k < FEATP; k += blockDim.x) {
            float v;
            if (k < E_)            v = erow[k];
            else if (k < E_ + 7)   v = casing[b * 7 + (k - E_)];
            else if (k < FEAT)     v = pos[b * 12 + (k - E_ - 7)];
            else                   v = 0.0f;
            xrow[k] = __float2half_rn(v);
        }
    } else if (b < M_ + G4H) {
        int j = b - M_;
        for (int k = threadIdx.x; k < FEATP; k += blockDim.x)
            g_wi0ph[(size_t)j * FEATP + k] =
                __float2half_rn((k < FEAT) ? wi0[(size_t)j * FEAT + k] : 0.0f);
    } else if (b < M_ + G4H + B_) {
        int r = b - M_ - G4H;
        const float* src = h_init0 + (size_t)r * H_;
        __half* dst = g_hinith + (size_t)r * H_;
        int k = threadIdx.x * 4;
        float4 v = *(const float4*)(src + k);
        *(__half2*)(dst + k)     = __floats2half2_rn(v.x, v.y);
        *(__half2*)(dst + k + 2) = __floats2half2_rn(v.z, v.w);
    } else if (b < M_ + 3 * G4H + B_) {
        int j = b - (M_ + G4H + B_);
        int sel = j >> 12, row = j & 4095;
        const float* src = (sel ? wh1 : wi1) + (size_t)row * H_;
        __half* dst = g_w1h[sel] + (size_t)row * H_;
        int k = threadIdx.x * 4;
        float4 v = *(const float4*)(src + k);
        *(__half2*)(dst + k)     = __floats2half2_rn(v.x, v.y);
        *(__half2*)(dst + k + 2) = __floats2half2_rn(v.z, v.w);
    } else {
        int j = b - (M_ + 3 * G4H + B_);         // 0..15
        __half* dst = g_dwh + (size_t)j * 2 * H_;
        if (j < C_) {
            const float* src = dec_w + (size_t)j * 2 * H_;
            for (int k = threadIdx.x * 4; k < 2 * H_; k += blockDim.x * 4) {
                float4 v = *(const float4*)(src + k);
                *(__half2*)(dst + k)     = __floats2half2_rn(v.x, v.y);
                *(__half2*)(dst + k + 2) = __floats2half2_rn(v.z, v.w);
            }
        } else {
            for (int k = threadIdx.x * 4; k < 2 * H_; k += blockDim.x * 4) {
                *(__half2*)(dst + k)     = __floats2half2_rn(0.f, 0.f);
                *(__half2*)(dst + k + 2) = __floats2half2_rn(0.f, 0.f);
            }
        }
    }
}

// ===========================================================================
// Kernel 2: FULLY-FUSED persistent layer-0 scan. ldmatrix.x4 for BOTH A and B
// (B x4 = 2 gates x 2 k-halves via per-lane addressing). Cross-step X
// prefetch keeps the cp.async ring primed over the step boundary.
// ===========================================================================
__global__ __launch_bounds__(256, 1) void k_lstm0_scan(
    const float* __restrict__ c_init0, const float* __restrict__ wh0,
    const float* __restrict__ bi0, const float* __restrict__ bh0) {
    extern __shared__ __half smh[];
    __half* Ws = smh;                                  // [64][1032]
    __half* Wx = smh + SCAN_WS_HALF;                   // [64][328]
    __half* Hs = Wx + SCAN_WX_HALF;                    // [3][128][72]
    float*  Bs = (float*)(Hs + SCAN_HS_HALF);          // [64]

    const int tid = threadIdx.x, lane = tid & 31, wid = tid >> 5;
    const int tg = lane & 3, gr = lane >> 2;
    const int wm = wid & 3, wn = wid >> 2;   // WM=4 (rows), WN=2 (col n8)
    const int mt = blockIdx.x >> 6;          // row-group 0..1
    const int mrow0 = mt * 128;
    const int n0 = (blockIdx.x & 63) * 16;   // per-gate col base

    // ---- one-time: wh0 slab -> Ws fp16 ----
    {
        int r = tid >> 2, q = tid & 3;       // r: 0..63 = g*16+nn
        int g = r >> 4, nn = r & 15;
        const float4* src = (const float4*)(wh0 + (size_t)(g * H_ + n0 + nn) * H_);
        __half* dst = Ws + (size_t)r * 1032;
        for (int k4 = q * 64; k4 < q * 64 + 64; k4++) {
            float4 v = src[k4];
            dst[k4 * 4 + 0] = __float2half_rn(v.x);
            dst[k4 * 4 + 1] = __float2half_rn(v.y);
            dst[k4 * 4 + 2] = __float2half_rn(v.z);
            dst[k4 * 4 + 3] = __float2half_rn(v.w);
        }
    }
    // ---- one-time: wi0 slab (fp16 padded) -> Wx via cp.async ----
    {
#pragma unroll
        for (int it = 0; it < 10; it++) {
            int idx = tid + it * 256;        // 0..2559
            int r = idx / 40, q = idx % 40;
            int g = r >> 4, nn = r & 15;
            cpa16(Wx + (size_t)r * 328 + q * 8,
                  g_wi0ph + (size_t)(g * H_ + n0 + nn) * FEATP + q * 8);
        }
    }
    if (tid < 64) {
        int g = tid >> 4, nn = tid & 15;
        Bs[tid] = bi0[g * H_ + n0 + nn] + bh0[g * H_ + n0 + nn];
    }
    CP_COMMIT();
    cp_wait<0>();

    // ---- ldmatrix per-lane address bases (bytes) ----
    const int lq = lane >> 3, lr = lane & 7;           // quad, row-in-quad
    const unsigned hsBase = smem_u32(Hs);
    unsigned aoff[2];
#pragma unroll
    for (int m2 = 0; m2 < 2; m2++)
        aoff[m2] = (unsigned)(((wm * 32 + m2 * 16 + ((lq & 1) << 3) + lr) * 72 +
                               ((lq >> 1) << 3)) * 2);
    // B x4 lanes: gsel2 = lane>>4 (gate within pair), ksel = (lane>>3)&1
    const int gsel2 = lane >> 4;
    const int ksel = (lane >> 3) & 1;
    const unsigned bW0 = smem_u32(Ws) +
        (unsigned)(((gsel2 * 16 + wn * 8 + lr) * 1032 + ksel * 8) * 2);
    const unsigned bX0 = smem_u32(Wx) +
        (unsigned)(((gsel2 * 16 + wn * 8 + lr) * 328 + ksel * 8) * 2);
    const unsigned pW = 32u * 1032u * 2u;   // gate-pair step (gates 2,3)
    const unsigned pX = 32u * 328u * 2u;

    // ---- c state in registers ----
    float creg[2][2][2];
#pragma unroll
    for (int mt2 = 0; mt2 < 2; mt2++)
#pragma unroll
        for (int hf = 0; hf < 2; hf++) {
            int m = mrow0 + wm * 32 + mt2 * 16 + hf * 8 + gr;
            float2 cv = *(const float2*)(c_init0 + (size_t)m * H_ + n0 + wn * 8 + 2 * tg);
            creg[mt2][hf][0] = cv.x;
            creg[mt2][hf][1] = cv.y;
        }

    float acc[4][2][4];
#pragma unroll
    for (int g = 0; g < 4; g++)
#pragma unroll
        for (int mt2 = 0; mt2 < 2; mt2++)
#pragma unroll
            for (int r = 0; r < 4; r++) acc[g][mt2][r] = 0.0f;

    __syncthreads();

    const int NCH = 21;    // 5 X-chunks + 16 h-chunks

    auto fill = [&](int ch, const __half* xb, const __half* hp) {
        __half* dst = Hs + (ch % 3) * (128 * 72);
        const __half* src;
        int stride, koff;
        if (ch < 5) { src = xb;  stride = FEATP; koff = ch * 64; }
        else        { src = hp;  stride = H_;    koff = (ch - 5) * 64; }
#pragma unroll
        for (int it = 0; it < 4; it++) {
            int idx = tid + it * 256, row = idx >> 3, q = idx & 7;
            cpa16(dst + row * 72 + q * 8,
                  src + (size_t)row * stride + koff + q * 8);
        }
    };

    // prologue (t = 0 X chunks)
    {
        const __half* xb0 = g_Xh + (size_t)mrow0 * FEATP;
        fill(0, xb0, nullptr); CP_COMMIT();
        fill(1, xb0, nullptr); CP_COMMIT();
    }

    for (int t = 0; t < T_; t++) {
        const __half* hprev = (t == 0) ? (g_hinith + (size_t)mrow0 * H_)
                                       : (g_h0h + ((size_t)(t - 1) * B_ + mrow0) * H_);
        const __half* xbase = g_Xh + ((size_t)t * B_ + mrow0) * FEATP;
        const __half* xnext = g_Xh + ((size_t)(t + 1) * B_ + mrow0) * FEATP;
        __half* hout = g_h0h + ((size_t)t * B_ + mrow0) * H_;
        __half* cout = g_c0h + ((size_t)t * B_ + mrow0) * H_;

        for (int i = 0; i < NCH; i++) {
            cp_wait<1>();
            __syncthreads();
            const unsigned HbA = hsBase + (unsigned)((i % 3) * (128 * 72 * 2));
            const bool isX = (i < 5);
            const unsigned bBase = isX ? bX0 : bW0;
            const unsigned pstep = isX ? pX : pW;
            const int kbase = isX ? i * 64 : (i - 5) * 64;
#pragma unroll
            for (int ks = 0; ks < 4; ks++) {
                unsigned a[2][4];
                ldsm4(a[0], HbA + aoff[0] + (unsigned)(ks * 32));
                ldsm4(a[1], HbA + aoff[1] + (unsigned)(ks * 32));
                const unsigned wk2 = (unsigned)((kbase + ks * 16) * 2);
                unsigned b01[4], b23[4];
                ldsm4(b01, bBase + wk2);
                ldsm4(b23, bBase + pstep + wk2);
                mma16(acc[0][0], a[0], b01 + 0); mma16(acc[0][1], a[1], b01 + 0);
                mma16(acc[1][0], a[0], b01 + 2); mma16(acc[1][1], a[1], b01 + 2);
                mma16(acc[2][0], a[0], b23 + 0); mma16(acc[2][1], a[1], b23 + 0);
                mma16(acc[3][0], a[0], b23 + 2); mma16(acc[3][1], a[1], b23 + 2);
            }
            if (i + 2 < NCH) {
                if (i + 2 == 5) {
                    if (tid == 0) {
                        unsigned tgt = (unsigned)(64 * t);
                        while (ldv(&g_cnt[mt]) < tgt) __nanosleep(32);
                    }
                    __threadfence();
                    __syncthreads();
                }
                fill(i + 2, xbase, hprev);
            } else if (t + 1 < T_) {
                fill(i + 2 - NCH, xnext, nullptr);   // next step X prefetch
            }
            CP_COMMIT();
        }

        // ---- fused gate epilogue; bias from SMEM, c stays in registers ----
#pragma unroll
        for (int mt2 = 0; mt2 < 2; mt2++)
#pragma unroll
            for (int hf = 0; hf < 2; hf++) {
                int ml = wm * 32 + mt2 * 16 + hf * 8 + gr;     // local row 0..127
                int lc = wn * 8 + 2 * tg;                      // col within gate
                int nc = n0 + lc;
                float h2v[2];
#pragma unroll
                for (int cc = 0; cc < 2; cc++) {
                    int r = hf * 2 + cc;
                    float pi = acc[0][mt2][r] + Bs[0 * 16 + lc + cc];
                    float pfv = acc[1][mt2][r] + Bs[1 * 16 + lc + cc];
                    float po = acc[2][mt2][r] + Bs[2 * 16 + lc + cc];
                    float pg = acc[3][mt2][r] + Bs[3 * 16 + lc + cc];
                    float c = sigmoidf_(pfv) * creg[mt2][hf][cc] + sigmoidf_(pi) * tanhf(pg);
                    creg[mt2][hf][cc] = c;
                    h2v[cc] = sigmoidf_(po) * tanhf(c);
                }
                *(__half2*)(hout + (size_t)ml * H_ + nc) = __floats2half2_rn(h2v[0], h2v[1]);
                *(__half2*)(cout + (size_t)ml * H_ + nc) =
                    __floats2half2_rn(creg[mt2][hf][0], creg[mt2][hf][1]);
            }
#pragma unroll
        for (int g = 0; g < 4; g++)
#pragma unroll
            for (int mt2 = 0; mt2 < 2; mt2++)
#pragma unroll
                for (int r = 0; r < 4; r++) acc[g][mt2][r] = 0.0f;

        __threadfence();
        __syncthreads();
        if (tid == 0) atomicAdd(&g_cnt[mt], 1u);
    }
}

// ===========================================================================
// Kernel 3: layer-1, fp16 MMA + ldmatrix (x4 for A and B), flip-reuse,
// 2 CTAs/SM. BM=256, BN=64 (4 gates x 16 cols); 8 warps WM=4 x WN=2.
// ===========================================================================
__global__ __launch_bounds__(256, 2) void k_lstm1(const float* __restrict__ bi1,
                                                  const float* __restrict__ bh1) {
    extern __shared__ __half sm1h[];

    const int m0 = blockIdx.y * 256;
    const int n0 = blockIdx.x * 16;
    const int tid = threadIdx.x, lane = tid & 31, wid = tid >> 5;
    const int wm = wid & 3, wn = wid >> 2;
    const int tg = lane & 3, gr = lane >> 2;

    // ldmatrix per-lane bases (bytes, relative to stage base)
    const int lq = lane >> 3, lr = lane & 7;
    unsigned aoffD[4], aoffF[4];
#pragma unroll
    for (int mti = 0; mti < 4; mti++) {
        int baseD = wm * 64 + mti * 16;
        aoffD[mti] = (unsigned)(((baseD + ((lq & 1) << 3) + lr) * 40 +
                                 ((lq >> 1) << 3)) * 2);
        int rowF = 255 - baseD - ((lq & 1) << 3) - lr;
        aoffF[mti] = (unsigned)((rowF * 40 + ((lq >> 1) << 3)) * 2);
    }
    const int gsel2 = lane >> 4;
    const int ksel = (lane >> 3) & 1;
    const unsigned boffP = (unsigned)(((gsel2 * 16 + wn * 8 + lr) * 40 + ksel * 8) * 2);
    const unsigned pB = 32u * 40u * 2u;     // gate-pair step
    const unsigned smBase = smem_u32(sm1h);

    float acc[4][4][4];
#pragma unroll
    for (int g = 0; g < 4; g++)
#pragma unroll
        for (int mti = 0; mti < 4; mti++)
#pragma unroll
            for (int r = 0; r < 4; r++) acc[g][mti][r] = 0.0f;

    auto fill = [&](int p) {
        int s = p % 3;
        int kk0 = p * 32;
        __half* dA = sm1h + s * L1_STAGE_HALF;
#pragma unroll
        for (int it = 0; it < 4; it++) {
            int idx = tid + it * 256, row = idx >> 2, q = idx & 3;
            cpa16(dA + row * 40 + q * 8,
                  g_h0h + (size_t)(m0 + row) * H_ + kk0 + q * 8);
        }
        __half* dB = dA + 256 * 40;
#pragma unroll
        for (int it = 0; it < 2; it++) {
            int idx = tid + it * 256, row = idx >> 2, q = idx & 3;
            const __half* W = g_w1h[row >> 6];
            int r2 = row & 63;
            int g = r2 >> 4, nn = r2 & 15;
            cpa16(dB + row * 40 + q * 8,
                  W + (size_t)(g * H_ + n0 + nn) * H_ + kk0 + q * 8);
        }
    };

    fill(0); CP_COMMIT();
    fill(1); CP_COMMIT();

    for (int p = 0; p < 32; p++) {
        cp_wait<1>();
        __syncthreads();
        const unsigned AbA = smBase + (unsigned)((p % 3) * L1_STAGE_HALF * 2);
        const unsigned BwA = AbA + 256 * 40 * 2;
        const unsigned BhA = BwA + 64 * 40 * 2;
#pragma unroll
        for (int ks = 0; ks < 2; ks++) {
            const unsigned k2 = (unsigned)(ks * 32);
            unsigned a[4][4];
            // ---- direct rows vs wi1 ----
#pragma unroll
            for (int mti = 0; mti < 4; mti++)
                ldsm4(a[mti], AbA + aoffD[mti] + k2);
            {
                unsigned b01[4], b23[4];
                ldsm4(b01, BwA + boffP + k2);
                ldsm4(b23, BwA + boffP + pB + k2);
#pragma unroll
                for (int mti = 0; mti < 4; mti++) {
                    mma16(acc[0][mti], a[mti], b01 + 0);
                    mma16(acc[1][mti], a[mti], b01 + 2);
                    mma16(acc[2][mti], a[mti], b23 + 0);
                    mma16(acc[3][mti], a[mti], b23 + 2);
                }
            }
            // ---- flipped rows vs wh1 ----
#pragma unroll
            for (int mti = 0; mti < 4; mti++)
                ldsm4(a[mti], AbA + aoffF[mti] + k2);
            {
                unsigned b01[4], b23[4];
                ldsm4(b01, BhA + boffP + k2);
                ldsm4(b23, BhA + boffP + pB + k2);
#pragma unroll
                for (int mti = 0; mti < 4; mti++) {
                    mma16(acc[0][mti], a[mti], b01 + 0);
                    mma16(acc[1][mti], a[mti], b01 + 2);
                    mma16(acc[2][mti], a[mti], b23 + 0);
                    mma16(acc[3][mti], a[mti], b23 + 2);
                }
            }
        }
        if (p + 2 < 32) fill(p + 2);
        CP_COMMIT();
    }

#pragma unroll
    for (int mti = 0; mti < 4; mti++)
#pragma unroll
        for (int hf = 0; hf < 2; hf++) {
            int m = m0 + wm * 64 + mti * 16 + hf * 8 + gr;
            int bq = m & 255;
            int mflip = m - bq + 255 - bq;
            const __half* cp = g_c0h + (size_t)mflip * H_;
            __half* hp = g_h1h + (size_t)m * H_;
            int nnb = n0 + wn * 8 + 2 * tg;
            float2 cv = __half22float2(*(const __half2*)(cp + nnb));
            float hv[2];
#pragma unroll
            for (int cc = 0; cc < 2; cc++) {
                int nn = nnb + cc;
                int r = hf * 2 + cc;
                float pi = acc[0][mti][r] + bi1[nn] + bh1[nn];
                float pf = acc[1][mti][r] + bi1[H_ + nn] + bh1[H_ + nn];
                float po = acc[2][mti][r] + bi1[2 * H_ + nn] + bh1[2 * H_ + nn];
                float pg = acc[3][mti][r] + bi1[3 * H_ + nn] + bh1[3 * H_ + nn];
                float c = sigmoidf_(pf) * (cc ? cv.y : cv.x) + sigmoidf_(pi) * tanhf(pg);
                hv[cc] = sigmoidf_(po) * tanhf(c);
            }
            *(__half2*)(hp + nnb) = __floats2half2_rn(hv[0], hv[1]);
        }
}

// ===========================================================================
// Kernel 4: decode as fp16 GEMM. (round-13 proven)
// ===========================================================================
__global__ __launch_bounds__(256, 1) void k_decode(const float* __restrict__ dec_b,
                                                   float* __restrict__ out) {
    extern __shared__ __half smd[];

    const int m0 = blockIdx.x * 256;
    const int tid = threadIdx.x, lane = tid & 31, wid = tid >> 5;
    const int tg = lane & 3, gr = lane >> 2;

    float acc[2][2][4];
#pragma unroll
    for (int mt = 0; mt < 2; mt++)
#pragma unroll
        for (int nt = 0; nt < 2; nt++)
#pragma unroll
            for (int r = 0; r < 4; r++) acc[mt][nt][r] = 0.0f;

    auto fill = [&](int p) {
        int s = p % 3;
        __half* dA = smd + s * DC_STAGE_HALF;
        const __half* hsrc = (p < 32) ? g_h0h : g_h1h;
        int kk0 = (p * 32) & (H_ - 1);
#pragma unroll
        for (int it = 0; it < 4; it++) {
            int idx = tid + it * 256, row = idx >> 2, q = idx & 3;
            cpa16(dA + row * 40 + q * 8,
                  hsrc + (size_t)(m0 + row) * H_ + kk0 + q * 8);
        }
        __half* dB = dA + 256 * 40;
        if (tid < 64) {
            int row = tid >> 2, q = tid & 3;
            cpa16(dB + row * 40 + q * 8,
                  g_dwh + (size_t)row * 2 * H_ + p * 32 + q * 8);
        }
    };

    fill(0); CP_COMMIT();
    fill(1); CP_COMMIT();

    for (int p = 0; p < 64; p++) {
        cp_wait<1>();
        __syncthreads();
        const __half* Ab = smd + (p % 3) * DC_STAGE_HALF;
        const __half* Bb = Ab + 256 * 40;
#pragma unroll
        for (int ks = 0; ks < 2; ks++) {
            const int ko = ks * 16 + 2 * tg;
            unsigned a[2][4];
#pragma unroll
            for (int mt = 0; mt < 2; mt++) {
                const __half* r0 = Ab + (wid * 32 + mt * 16 + gr) * 40 + ko;
                a[mt][0] = *(const unsigned*)(r0);
                a[mt][1] = *(const unsigned*)(r0 + 8 * 40);
                a[mt][2] = *(const unsigned*)(r0 + 8);
                a[mt][3] = *(const unsigned*)(r0 + 8 * 40 + 8);
            }
#pragma unroll
            for (int nt = 0; nt < 2; nt++) {
                const __half* rb = Bb + (nt * 8 + gr) * 40 + ko;
                unsigned b[2];
                b[0] = *(const unsigned*)(rb);
                b[1] = *(const unsigned*)(rb + 8);
#pragma unroll
                for (int mt = 0; mt < 2; mt++) mma16(acc[mt][nt], a[mt], b);
            }
        }
        if (p + 2 < 64) fill(p + 2);
        CP_COMMIT();
    }

#pragma unroll
    for (int mt = 0; mt < 2; mt++)
#pragma unroll
        for (int hf = 0; hf < 2; hf++) {
            int m = m0 + wid * 32 + mt * 16 + hf * 8 + gr;
            float* op = out + (size_t)m * C_;
#pragma unroll
            for (int nt = 0; nt < 2; nt++)
#pragma unroll
                for (int cc = 0; cc < 2; cc++) {
                    int c = nt * 8 + 2 * tg + cc;
                    if (c < C_)
                        op[c] = acc[mt][nt][hf * 2 + cc] + dec_b[c];
                }
        }
}

// ===========================================================================
// Launch
// ===========================================================================
extern "C" void kernel_launch(void* const* d_in, const int* in_sizes, int n_in,
                              void* d_out, int out_size) {
    const int*   tokens = (const int*)d_in[0];
    const float* casing = (const float*)d_in[1];
    const float* pos    = (const float*)d_in[2];
    const float* emb    = (const float*)d_in[3];
    const float* wi0    = (const float*)d_in[4];
    const float* bi0    = (const float*)d_in[5];
    const float* wh0    = (const float*)d_in[6];
    const float* bh0    = (const float*)d_in[7];
    const float* wi1    = (const float*)d_in[8];
    const float* bi1    = (const float*)d_in[9];
    const float* wh1    = (const float*)d_in[10];
    const float* bh1    = (const float*)d_in[11];
    const float* dec_w  = (const float*)d_in[12];
    const float* dec_b  = (const float*)d_in[13];
    const float* h_init = (const float*)d_in[14];
    const float* c_init = (const float*)d_in[15];
    float* out = (float*)d_out;

    (void)in_sizes; (void)n_in; (void)out_size;

    cudaFuncSetAttribute(k_lstm0_scan, cudaFuncAttributeMaxDynamicSharedMemorySize,
                         SCAN_SMEM);
    cudaFuncSetAttribute(k_lstm1, cudaFuncAttributeMaxDynamicSharedMemorySize,
                         L1_SMEM);
    cudaFuncSetAttribute(k_decode, cudaFuncAttributeMaxDynamicSharedMemorySize,
                         DC_SMEM);

    k_reset<<<1, 2>>>();
    k_build<<<M_ + 3 * G4H + B_ + 16, 256>>>(tokens, casing, pos, emb,
                                             wi0, wi1, wh1, h_init, dec_w);
    k_lstm0_scan<<<SCAN_NCTA, 256, SCAN_SMEM>>>(c_init, wh0, bi0, bh0);
    k_lstm1<<<dim3(H_ / 16, M_ / 256), 256, L1_SMEM>>>(bi1, bh1);
    k_decode<<<M_ / 256, 256, DC_SMEM>>>(dec_b, out);
}